// round 17
// baseline (speedup 1.0000x reference)
#include <cuda_runtime.h>
#include <cuda_bf16.h>
#include <cstdint>

#define N_NODES 100000
#define SS 2
#define GG 8
#define E_EDGES 400000
#define MID 256
#define LL 4
#define IN_CH 265
#define IN_STRIDE 288
#define M_ROWS (SS * N_NODES)            // 200000
#define M64TILES ((M_ROWS + 63) / 64)    // 3125

#define NSB 98                           // scan blocks
#define PRE_KT 9                         // 288/32 k-tiles for pre GEMM
#define NBTILES (2 * PRE_KT + 16 * 8)    // 18 pre + 128 layer tiles = 146

// A/B smem tile layout: [row/n][kpair stride 20 b32], real kp 0..15
#define B_STRIDE 20
#define NTILE_B32 (128 * B_STRIDE)       // 2560 u32 per 128-n weight tile
#define A_STRIDE 20

// ---------------- device scratch (no allocation allowed) ----------------
__device__ float    g_X0 [(size_t)M_ROWS * IN_STRIDE];
__device__ float    g_XA [(size_t)M_ROWS * MID];
__device__ float    g_XB [(size_t)M_ROWS * MID];
__device__ float    g_P  [(size_t)M_ROWS * 512];   // per-layer projections
__device__ uint32_t g_Bhi[(size_t)NBTILES * NTILE_B32];
__device__ uint32_t g_Blo[(size_t)NBTILES * NTILE_B32];
__device__ int   g_deg_fwd[N_NODES],      g_deg_rev[N_NODES];
__device__ int   g_rowstart_fwd[N_NODES + 1], g_rowstart_rev[N_NODES + 1];
__device__ int   g_cursor_fwd[N_NODES],   g_cursor_rev[N_NODES];
__device__ float g_inv_fwd[N_NODES],      g_inv_rev[N_NODES];
__device__ int   g_csr_fwd[E_EDGES],      g_csr_rev[E_EDGES];
__device__ int   g_bsum[2][NSB];
__device__ float g_out_acc[GG * SS];

__device__ __forceinline__ float* bufptr(int sel) {
    switch (sel) {
        case 0:  return g_X0;
        case 1:  return g_XA;
        case 2:  return g_XB;
        default: return g_P;
    }
}

// ---------------- helpers ----------------
__device__ __forceinline__ uint32_t pack_hi(float x, float y, uint32_t& lo_out) {
    __nv_bfloat16 hx = __float2bfloat16(x);
    __nv_bfloat16 hy = __float2bfloat16(y);
    __nv_bfloat16 lx = __float2bfloat16(x - __bfloat162float(hx));
    __nv_bfloat16 ly = __float2bfloat16(y - __bfloat162float(hy));
    lo_out = ((uint32_t)__bfloat16_as_ushort(ly) << 16) | __bfloat16_as_ushort(lx);
    return ((uint32_t)__bfloat16_as_ushort(hy) << 16) | __bfloat16_as_ushort(hx);
}

__device__ __forceinline__ void mma_bf16(float* d, const uint32_t* a,
                                         uint32_t b0, uint32_t b1) {
    asm volatile(
        "mma.sync.aligned.m16n8k16.row.col.f32.bf16.bf16.f32 "
        "{%0,%1,%2,%3}, {%4,%5,%6,%7}, {%8,%9}, {%0,%1,%2,%3};"
        : "+f"(d[0]), "+f"(d[1]), "+f"(d[2]), "+f"(d[3])
        : "r"(a[0]), "r"(a[1]), "r"(a[2]), "r"(a[3]), "r"(b0), "r"(b1));
}

// ---------------- graph preprocessing ----------------
__global__ void k_zero() {
    int i = blockIdx.x * blockDim.x + threadIdx.x;
    if (i < N_NODES) { g_deg_fwd[i] = 0; g_deg_rev[i] = 0; }
    if (i < GG * SS) g_out_acc[i] = 0.f;
}

__global__ void k_deg(const int* __restrict__ ei) {
    int e = blockIdx.x * blockDim.x + threadIdx.x;
    if (e >= E_EDGES) return;
    atomicAdd(&g_deg_fwd[ei[E_EDGES + e]], 1);
    atomicAdd(&g_deg_rev[ei[e]], 1);
}

__global__ void k_blocksum() {
    __shared__ int sh[256];
    int dir = blockIdx.y;
    const int* deg = dir ? g_deg_rev : g_deg_fwd;
    int base = blockIdx.x * 1024 + threadIdx.x * 4;
    int s = 0;
    #pragma unroll
    for (int j = 0; j < 4; j++) { int i = base + j; if (i < N_NODES) s += deg[i]; }
    sh[threadIdx.x] = s;
    __syncthreads();
    for (int off = 128; off > 0; off >>= 1) {
        if (threadIdx.x < off) sh[threadIdx.x] += sh[threadIdx.x + off];
        __syncthreads();
    }
    if (threadIdx.x == 0) g_bsum[dir][blockIdx.x] = sh[0];
}

__global__ void k_scanb() {
    int t = threadIdx.x;
    if (t < 2) {
        int run = 0;
        int* bs = g_bsum[t];
        for (int b = 0; b < NSB; b++) { int v = bs[b]; bs[b] = run; run += v; }
    }
    if (t == 0) { g_rowstart_fwd[N_NODES] = E_EDGES; g_rowstart_rev[N_NODES] = E_EDGES; }
}

__global__ void k_scatter() {
    __shared__ int sh[256];
    int dir = blockIdx.y;
    const int* deg = dir ? g_deg_rev : g_deg_fwd;
    int* rowstart  = dir ? g_rowstart_rev : g_rowstart_fwd;
    int* cursor    = dir ? g_cursor_rev   : g_cursor_fwd;
    float* inv     = dir ? g_inv_rev      : g_inv_fwd;
    int t = threadIdx.x;
    int base = blockIdx.x * 1024 + t * 4;
    int d[4]; int s = 0;
    #pragma unroll
    for (int j = 0; j < 4; j++) { int i = base + j; d[j] = (i < N_NODES) ? deg[i] : 0; s += d[j]; }
    sh[t] = s;
    __syncthreads();
    for (int off = 1; off < 256; off <<= 1) {
        int v = (t >= off) ? sh[t - off] : 0;
        __syncthreads();
        sh[t] += v;
        __syncthreads();
    }
    int run = g_bsum[dir][blockIdx.x] + sh[t] - s;
    #pragma unroll
    for (int j = 0; j < 4; j++) {
        int i = base + j;
        if (i < N_NODES) {
            rowstart[i] = run;
            cursor[i]   = run;
            inv[i]      = 1.0f / (float)(d[j] > 0 ? d[j] : 1);
            run += d[j];
        }
    }
}

__global__ void k_fill(const int* __restrict__ ei) {
    int e = blockIdx.x * blockDim.x + threadIdx.x;
    if (e >= E_EDGES) return;
    int s = ei[e], t = ei[E_EDGES + e];
    g_csr_fwd[atomicAdd(&g_cursor_fwd[t], 1)] = s;
    g_csr_rev[atomicAdd(&g_cursor_rev[s], 1)] = t;
}

// ---------------- feature assembly (stride-288, zero padded) ----------------
__global__ void k_assemble(const float* __restrict__ x_feat,
                           const float* __restrict__ dim_feat,
                           const float* __restrict__ layout_feat,
                           const float* __restrict__ tile_feat,
                           const float* __restrict__ opcode_embed,
                           const int* __restrict__ node_opcode,
                           const int* __restrict__ batch) {
    int m = blockIdx.x;
    int s = m / N_NODES;
    int n = m - s * N_NODES;
    int opc = node_opcode[n];
    int g   = batch[n];
    float* dst = g_X0 + (size_t)m * IN_STRIDE;
    for (int c = threadIdx.x; c < IN_STRIDE; c += blockDim.x) {
        float v;
        if (c < 53)       v = x_feat[(size_t)n * 53 + c];
        else if (c < 85)  v = opcode_embed[opc * 32 + (c - 53)];
        else if (c < 223) v = dim_feat[(size_t)n * 138 + (c - 85)];
        else if (c < 247) v = layout_feat[((size_t)n * SS + s) * 24 + (c - 223)];
        else if (c < 265) v = tile_feat[((size_t)g * SS + s) * 18 + (c - 247)];
        else              v = 0.f;
        dst[c] = v;
    }
}

// ---------------- weight prep: transpose + bf16 hi/lo split + pack ----------------
// pre tiles 0..17: tile = nt*9 + kt   (nt 0..1, kt 0..8), source preW
// layer tiles 18+: tile = 18 + i*32 + nt*8 + kt; nt: 0=convWl 1=convWr 2=revWl 3=revWr
__global__ void k_prepB(const float* __restrict__ preW,
                        const float* __restrict__ convWl, const float* __restrict__ convWr,
                        const float* __restrict__ revWl,  const float* __restrict__ revWr) {
    int tile = blockIdx.x;
    uint32_t* hi = g_Bhi + (size_t)tile * NTILE_B32;
    uint32_t* lo = g_Blo + (size_t)tile * NTILE_B32;
    for (int idx = threadIdx.x; idx < 2048; idx += blockDim.x) {
        int n  = idx >> 4;     // 0..127 output channel within tile
        int kp = idx & 15;     // bf16x2 pair within k=32
        float w[2];
        #pragma unroll
        for (int h = 0; h < 2; h++) {
            int kl = kp * 2 + h;
            float v = 0.f;
            if (tile < 2 * PRE_KT) {
                int nt = tile / PRE_KT, kt = tile % PRE_KT;
                int k = kt * 32 + kl;
                if (k < IN_CH) v = preW[(size_t)k * MID + nt * 128 + n];
            } else {
                int t2 = tile - 2 * PRE_KT;
                int i  = t2 / 32;
                int r  = t2 % 32;
                int nt = r / 8, kt = r % 8;
                int k = kt * 32 + kl;
                const float* W;
                if (nt == 0)      W = convWl;
                else if (nt == 1) W = convWr;
                else if (nt == 2) W = revWl;
                else              W = revWr;
                v = W[(size_t)i * 32768 + (size_t)k * 128 + n];
            }
            w[h] = v;
        }
        uint32_t l;
        uint32_t hpack = pack_hi(w[0], w[1], l);
        hi[n * B_STRIDE + kp] = hpack;
        lo[n * B_STRIDE + kp] = l;
    }
}

// ---------------- mma.sync bf16 split GEMM, 64x256 block tile ----------------
// C[:, bx*256 : +256] (row stride cstride) = A @ Bprepped [ + bias, relu if bias ]
// 128 threads = 4 warps side-by-side in n; warp tile 64x64; BK=32.
// n-group bx uses the two 128-n weight tiles nt = 2bx, 2bx+1:
//   tile(nt,kt) = tb0 + nt*nkt + kt
__global__ void __launch_bounds__(128) k_mgemm(
    int asel, int astride,
    const float* __restrict__ bias,           // nullptr -> raw output (no relu)
    int csel, int cstride, int tb0, int nkt)
{
    __shared__ uint32_t sAh[64 * A_STRIDE];
    __shared__ uint32_t sAl[64 * A_STRIDE];
    __shared__ uint32_t sBh[256 * B_STRIDE];
    __shared__ uint32_t sBl[256 * B_STRIDE];

    const int tid  = threadIdx.x;
    const int warp = tid >> 5, lane = tid & 31;
    const int wn = warp * 64;
    const int lr = lane >> 2;
    const int lc = lane & 3;
    const int bm = blockIdx.y * 64;
    const int t0 = tb0 + (2 * blockIdx.x)     * nkt;
    const int t1 = tb0 + (2 * blockIdx.x + 1) * nkt;

    const float* A = bufptr(asel);

    float acc[4][8][4];
    #pragma unroll
    for (int mf = 0; mf < 4; mf++)
        #pragma unroll
        for (int nf = 0; nf < 8; nf++)
            #pragma unroll
            for (int r = 0; r < 4; r++) acc[mf][nf][r] = 0.f;

    for (int kt = 0; kt < nkt; kt++) {
        int k0 = kt * 32;

        // ---- load A tile 64x32 fp32 -> split bf16 hi/lo packed (512 float4) ----
        #pragma unroll
        for (int i = 0; i < 4; i++) {
            int idx = i * 128 + tid;              // 0..511
            int row = idx >> 3, q = idx & 7;
            int gm = bm + row;
            float4 v = make_float4(0.f, 0.f, 0.f, 0.f);
            if (gm < M_ROWS) v = *(const float4*)(A + (size_t)gm * astride + k0 + q * 4);
            uint32_t l0, l1;
            uint32_t h0 = pack_hi(v.x, v.y, l0);
            uint32_t h1 = pack_hi(v.z, v.w, l1);
            int base = row * A_STRIDE + q * 2;
            sAh[base] = h0; sAh[base + 1] = h1;
            sAl[base] = l0; sAl[base + 1] = l1;
        }
        // ---- copy two B 128-n tiles (pre-packed): 2 x 640 int4 ----
        {
            const int4* bh0 = (const int4*)(g_Bhi + (size_t)(t0 + kt) * NTILE_B32);
            const int4* bl0 = (const int4*)(g_Blo + (size_t)(t0 + kt) * NTILE_B32);
            const int4* bh1 = (const int4*)(g_Bhi + (size_t)(t1 + kt) * NTILE_B32);
            const int4* bl1 = (const int4*)(g_Blo + (size_t)(t1 + kt) * NTILE_B32);
            int4* dh = (int4*)sBh;
            int4* dl = (int4*)sBl;
            #pragma unroll
            for (int i = 0; i < 5; i++) {
                dh[i * 128 + tid]       = bh0[i * 128 + tid];
                dl[i * 128 + tid]       = bl0[i * 128 + tid];
                dh[640 + i * 128 + tid] = bh1[i * 128 + tid];
                dl[640 + i * 128 + tid] = bl1[i * 128 + tid];
            }
        }
        __syncthreads();

        // ---- compute: 2 k16 steps ----
        #pragma unroll
        for (int ks = 0; ks < 2; ks++) {
            uint32_t ah[4][4], al[4][4];
            int kp = ks * 8 + lc;
            #pragma unroll
            for (int mf = 0; mf < 4; mf++) {
                int row = mf * 16 + lr;
                ah[mf][0] = sAh[row * A_STRIDE + kp];
                ah[mf][1] = sAh[(row + 8) * A_STRIDE + kp];
                ah[mf][2] = sAh[row * A_STRIDE + kp + 4];
                ah[mf][3] = sAh[(row + 8) * A_STRIDE + kp + 4];
                al[mf][0] = sAl[row * A_STRIDE + kp];
                al[mf][1] = sAl[(row + 8) * A_STRIDE + kp];
                al[mf][2] = sAl[row * A_STRIDE + kp + 4];
                al[mf][3] = sAl[(row + 8) * A_STRIDE + kp + 4];
            }
            #pragma unroll
            for (int nf = 0; nf < 8; nf++) {
                int n = wn + nf * 8 + lr;
                uint32_t bh0 = sBh[n * B_STRIDE + kp];
                uint32_t bh1 = sBh[n * B_STRIDE + kp + 4];
                uint32_t bl0 = sBl[n * B_STRIDE + kp];
                uint32_t bl1 = sBl[n * B_STRIDE + kp + 4];
                #pragma unroll
                for (int mf = 0; mf < 4; mf++) {
                    mma_bf16(acc[mf][nf], ah[mf], bh0, bh1);
                    mma_bf16(acc[mf][nf], al[mf], bh0, bh1);
                    mma_bf16(acc[mf][nf], ah[mf], bl0, bl1);
                }
            }
        }
        __syncthreads();
    }

    // ---- epilogue ----
    float* C = bufptr(csel);
    const bool dorelu = (bias != nullptr);
    #pragma unroll
    for (int mf = 0; mf < 4; mf++) {
        int r0 = bm + mf * 16 + lr;
        int r1 = r0 + 8;
        #pragma unroll
        for (int nf = 0; nf < 8; nf++) {
            int ncol = wn + nf * 8 + lc * 2;            // within 256-wide group
            int col  = blockIdx.x * 256 + ncol;
            float b0 = dorelu ? bias[col] : 0.f;
            float b1 = dorelu ? bias[col + 1] : 0.f;
            if (r0 < M_ROWS) {
                float2 v;
                v.x = acc[mf][nf][0] + b0;
                v.y = acc[mf][nf][1] + b1;
                if (dorelu) { v.x = fmaxf(v.x, 0.f); v.y = fmaxf(v.y, 0.f); }
                *(float2*)(C + (size_t)r0 * cstride + col) = v;
            }
            if (r1 < M_ROWS) {
                float2 v;
                v.x = acc[mf][nf][2] + b0;
                v.y = acc[mf][nf][3] + b1;
                if (dorelu) { v.x = fmaxf(v.x, 0.f); v.y = fmaxf(v.y, 0.f); }
                *(float2*)(C + (size_t)r1 * cstride + col) = v;
            }
        }
    }
}

// ---------------- fused aggregate + combine + relu + (optional head) ----------------
// P[m][512] = [Pl_f | Pr_f | Pl_r | Pr_r]
// o(n,c)     = relu(inv_f * sum_{j->n} Pl_f[j][c] + Pr_f[n][c] + bf[c])
// o(n,128+c) = relu(inv_r * sum_{n->j} Pl_r[j][c] + Pr_r[n][c] + br[c])
// If hW: out_acc[batch[n]*SS+s] += sum_c o(s,n,c)*hW[c]  (both samples)
__global__ void __launch_bounds__(128) k_combine(int osel, int writeO,
                                                 const float* __restrict__ bf,
                                                 const float* __restrict__ br,
                                                 const float* __restrict__ hW,
                                                 const int* __restrict__ batch) {
    const float* __restrict__ P = g_P;
    float* O = bufptr(osel);
    int n = blockIdx.x, c = threadIdx.x;

    int fb = g_rowstart_fwd[n], fe = g_rowstart_fwd[n + 1];
    int rb = g_rowstart_rev[n], re = g_rowstart_rev[n + 1];

    float af0 = 0.f, af1 = 0.f, ar0 = 0.f, ar1 = 0.f;
    for (int e = fb; e < fe; e++) {
        int src = g_csr_fwd[e];
        af0 += P[(size_t)src * 512 + c];
        af1 += P[(size_t)(N_NODES + src) * 512 + c];
    }
    for (int e = rb; e < re; e++) {
        int src = g_csr_rev[e];
        ar0 += P[(size_t)src * 512 + 256 + c];
        ar1 += P[(size_t)(N_NODES + src) * 512 + 256 + c];
    }
    float invf = g_inv_fwd[n], invr = g_inv_rev[n];
    float bfc = bf[c], brc = br[c];

    float sf0 = P[(size_t)n * 512 + 128 + c];
    float sf1 = P[(size_t)(N_NODES + n) * 512 + 128 + c];
    float sr0 = P[(size_t)n * 512 + 384 + c];
    float sr1 = P[(size_t)(N_NODES + n) * 512 + 384 + c];

    float o0 = fmaxf(af0 * invf + sf0 + bfc, 0.f);   // s0, col c
    float o1 = fmaxf(ar0 * invr + sr0 + brc, 0.f);   // s0, col 128+c
    float o2 = fmaxf(af1 * invf + sf1 + bfc, 0.f);   // s1, col c
    float o3 = fmaxf(ar1 * invr + sr1 + brc, 0.f);   // s1, col 128+c

    if (writeO) {
        O[(size_t)n * MID + c]                   = o0;
        O[(size_t)n * MID + 128 + c]             = o1;
        O[(size_t)(N_NODES + n) * MID + c]       = o2;
        O[(size_t)(N_NODES + n) * MID + 128 + c] = o3;
    }

    if (hW) {
        __shared__ float red[8];
        float w0 = hW[c], w1 = hW[128 + c];
        float p0 = o0 * w0 + o1 * w1;
        float p1 = o2 * w0 + o3 * w1;
        #pragma unroll
        for (int o = 16; o > 0; o >>= 1) {
            p0 += __shfl_down_sync(0xffffffffu, p0, o);
            p1 += __shfl_down_sync(0xffffffffu, p1, o);
        }
        int wid = c >> 5;
        if ((c & 31) == 0) { red[wid] = p0; red[4 + wid] = p1; }
        __syncthreads();
        if (c == 0) {
            float P0 = red[0] + red[1] + red[2] + red[3];
            float P1 = red[4] + red[5] + red[6] + red[7];
            int g = batch[n];
            atomicAdd(&g_out_acc[g * SS + 0], P0);
            atomicAdd(&g_out_acc[g * SS + 1], P1);
        }
    }
}

__global__ void k_out(float* __restrict__ out, const float* __restrict__ headb) {
    int i = threadIdx.x;
    if (i < GG * SS) out[i] = g_out_acc[i] + headb[0];
}

// ---------------- driver ----------------
extern "C" void kernel_launch(void* const* d_in, const int* in_sizes, int n_in,
                              void* d_out, int out_size) {
    const float* x_feat       = (const float*)d_in[0];
    const float* dim_feat     = (const float*)d_in[1];
    const float* layout_feat  = (const float*)d_in[2];
    const float* tile_feat    = (const float*)d_in[3];
    const float* opcode_embed = (const float*)d_in[4];
    const float* preW         = (const float*)d_in[5];
    const float* preb         = (const float*)d_in[6];
    const float* convWl       = (const float*)d_in[7];
    const float* convWr       = (const float*)d_in[8];
    const float* convb        = (const float*)d_in[9];
    const float* revWl        = (const float*)d_in[10];
    const float* revWr        = (const float*)d_in[11];
    const float* revb         = (const float*)d_in[12];
    const float* headW        = (const float*)d_in[13];
    const float* headb        = (const float*)d_in[14];
    const int*   node_opcode  = (const int*)d_in[15];
    const int*   batch        = (const int*)d_in[16];
    const int*   edge_index   = (const int*)d_in[17];
    float* out = (float*)d_out;

    // graph structure
    k_zero    <<<(N_NODES + 255) / 256, 256>>>();
    k_deg     <<<(E_EDGES + 255) / 256, 256>>>(edge_index);
    k_blocksum<<<dim3(NSB, 2), 256>>>();
    k_scanb   <<<1, 32>>>();
    k_scatter <<<dim3(NSB, 2), 256>>>();
    k_fill    <<<(E_EDGES + 255) / 256, 256>>>(edge_index);

    // features + weights
    k_assemble<<<M_ROWS, 288>>>(x_feat, dim_feat, layout_feat, tile_feat,
                                opcode_embed, node_opcode, batch);
    k_prepB<<<NBTILES, 256>>>(preW, convWl, convWr, revWl, revWr);

    // pre-linear: XA = relu(X0 @ preW + preb)   (one 256-wide n-group)
    k_mgemm<<<dim3(1, M64TILES), 128>>>(0, IN_STRIDE, preb, 1, MID, 0, PRE_KT);

    for (int i = 0; i < LL; i++) {
        int insel  = (i % 2 == 0) ? 1 : 2;
        int outsel = (i % 2 == 0) ? 2 : 1;
        // P = X @ [Wl_f | Wr_f | Wl_r | Wr_r]   (two 256-wide n-groups, raw)
        k_mgemm<<<dim3(2, M64TILES), 128>>>(insel, MID, nullptr, 3, 512,
                                            2 * PRE_KT + i * 32, 8);
        // fused gather + self + bias + relu (+ head for last 2 layers)
        const float* hW = (i >= LL - 2) ? (headW + (i - (LL - 2)) * MID) : nullptr;
        int writeO = (i < LL - 1) ? 1 : 0;
        k_combine<<<N_NODES, 128>>>(outsel, writeO, convb + i * 128, revb + i * 128,
                                    hW, batch);
    }

    k_out<<<1, 32>>>(out, headb);
}